// round 4
// baseline (speedup 1.0000x reference)
#include <cuda_runtime.h>
#include <math.h>

#define BB 4
#define NN 32
#define DD 128
#define HH 8
#define NCC 27
#define DFF 512
#define LL (NCC*NN)        // 864
#define ROWS (BB*LL)       // 3456
#define GRID 216
#define TPB 256

// ---------------- scratch (static device globals; no allocation) -------------
__device__ __align__(16) float g_base[ROWS*DD];
__device__ __align__(16) float g_tvec[ROWS*DD];
__device__ __align__(16) float g_Pk[ROWS*DD];
__device__ __align__(16) float g_Pv[ROWS*DD];
__device__ __align__(16) float g_Tk[ROWS*DD];
__device__ __align__(16) float g_Tv[ROWS*DD];
__device__ float g_mb[ROWS], g_ssb[ROWS];
__device__ float g_mt[ROWS], g_sst[ROWS];
__device__ float g_sdiag[ROWS];
__device__ float g_S[BB*NCC*NN*NN];
__device__ float g_Q[BB*NN*DD];
__device__ __align__(16) float g_y[BB*NN*DD];
__device__ __align__(16) float g_hn2[BB*NN*DD];
__device__ float g_uk[DD], g_uv[DD], g_ck[DD], g_cv[DD];

// barrier state (zero-initialized; self-cleaning across launches)
__device__ unsigned g_cnt[3];
__device__ volatile unsigned g_sense[3];

__inline__ __device__ float warpSum(float v){
    #pragma unroll
    for (int o = 16; o; o >>= 1) v += __shfl_down_sync(0xffffffffu, v, o);
    return v;
}

// global barrier k (0..2). All GRID blocks co-resident by construction.
__device__ __forceinline__ void gbar(int k){
    __syncthreads();
    if (threadIdx.x == 0){
        __threadfence();
        atomicAdd(&g_cnt[k], 1u);                 // RED (result unused)
        if (blockIdx.x == 0){
            while (atomicAdd(&g_cnt[k], 0u) < (unsigned)GRID) { }
            if (k > 0){ g_cnt[k-1] = 0u; g_sense[k-1] = 0u; }  // clean previous
            __threadfence();
            g_sense[k] = 1u;
        } else {
            while (g_sense[k] == 0u) { }
        }
        __threadfence();
    }
    __syncthreads();
}

__global__ void __launch_bounds__(TPB, 2)
k_fused(const float* __restrict__ x, const int* __restrict__ mask,
        const float* __restrict__ coords,
        const float* __restrict__ Wp, const float* __restrict__ bp,
        const float* __restrict__ Wq, const float* __restrict__ bq,
        const float* __restrict__ Wk, const float* __restrict__ bk,
        const float* __restrict__ Wv, const float* __restrict__ bv,
        const float* __restrict__ Wo, const float* __restrict__ bo,
        const float* __restrict__ g1, const float* __restrict__ b1,
        const float* __restrict__ g2, const float* __restrict__ b2,
        const float* __restrict__ W1, const float* __restrict__ bf1,
        const float* __restrict__ W2, const float* __restrict__ bf2,
        float* __restrict__ out)
{
    __shared__ __align__(16) float sbuf[9920];   // ~39.7 KB, reused per phase
    __shared__ float sred[2][4][8];
    __shared__ float rsm[4][2], stat[2];
    __shared__ int   mk[32];

    int tid = threadIdx.x, bid = blockIdx.x;

    // entry: clean last barrier's state from previous launch (graph replay safe)
    if (bid == 0 && tid == 0){ g_cnt[2] = 0u; g_sense[2] = 0u; }

    // ================= PHASE A: base/tvec + per-row stats + self-dot + uc =====
    {
        int half = tid >> 7, d = tid & 127;
        #pragma unroll 1
        for (int it = 0; it < 8; it++){
            int r = bid*16 + it*2 + half;          // 216*16 = 3456 rows
            int n = r & 31;
            int b = r / (NCC*NN);
            float c0 = coords[r*3+0], c1 = coords[r*3+1], c2 = coords[r*3+2];
            float t  = c0*Wp[d] + c1*Wp[DD+d] + c2*Wp[2*DD+d];
            float bs = x[(b*NN+n)*DD + d] + t + bp[d];
            g_tvec[r*DD + d] = t;
            g_base[r*DD + d] = bs;
            float s0 = warpSum(t), s1 = warpSum(t*t), s2 = warpSum(bs),
                  s3 = warpSum(bs*bs), s4 = warpSum(bs*t);
            int lane = d & 31, w = d >> 5;
            if (lane == 0){
                sred[half][w][0]=s0; sred[half][w][1]=s1; sred[half][w][2]=s2;
                sred[half][w][3]=s3; sred[half][w][4]=s4;
            }
            __syncthreads();
            if (d < 5){
                float a = sred[half][0][d]+sred[half][1][d]+sred[half][2][d]+sred[half][3][d];
                if      (d == 0) g_mt[r]    = a * (1.0f/128.0f);
                else if (d == 1) g_sst[r]   = a;
                else if (d == 2) g_mb[r]    = a * (1.0f/128.0f);
                else if (d == 3) g_ssb[r]   = a;
                else             g_sdiag[r] = a;
            }
            __syncthreads();
        }
        // uc: blocks 0..127 compute one output dim each
        if (bid < 128){
            int dd = bid;
            if (tid < 128){
                int k = tid;
                float g = g1[k], bb = b1[k];
                float wk = Wk[k*128 + dd], wv = Wv[k*128 + dd];
                float s0 = warpSum(g*wk), s1 = warpSum(g*wv),
                      s2 = warpSum(bb*wk), s3 = warpSum(bb*wv);
                if ((tid & 31) == 0){
                    sred[0][tid>>5][0]=s0; sred[0][tid>>5][1]=s1;
                    sred[0][tid>>5][2]=s2; sred[0][tid>>5][3]=s3;
                }
            }
            __syncthreads();
            if (tid < 4){
                float a = sred[0][0][tid]+sred[0][1][tid]+sred[0][2][tid]+sred[0][3][tid];
                if      (tid == 0) g_uk[dd] = a;
                else if (tid == 1) g_uv[dd] = a;
                else if (tid == 2) g_ck[dd] = a + bk[dd];
                else               g_cv[dd] = a + bv[dd];
            }
        }
    }
    gbar(0);

    // ================= PHASE B: P/T GEMMs + S dots + Q projections ============
    {
        // GEMM tile: 32 rows x 128 cols, dual weights. tile = bid (216 tiles)
        float (*As)[128] = (float(*)[128])sbuf;
        int m0 = bid * 32;
        const float* src; float* outK; float* outV; int ro;
        if (m0 < ROWS){ src = g_base + m0*DD;        outK = g_Pk; outV = g_Pv; ro = m0; }
        else          { src = g_tvec + (m0-ROWS)*DD; outK = g_Tk; outV = g_Tv; ro = m0-ROWS; }

        for (int idx = tid; idx < 32*128; idx += TPB){
            int dd = idx & 127;
            As[idx >> 7][dd] = src[idx] * g1[dd];
        }
        __syncthreads();

        int j = tid & 127;
        const float* W = (tid < 128) ? Wk : Wv;
        float*     po  = (tid < 128) ? outK : outV;

        float acc[32];
        #pragma unroll
        for (int r = 0; r < 32; r++) acc[r] = 0.0f;

        for (int k4 = 0; k4 < 32; k4++){
            float w0 = W[(4*k4+0)*128 + j];
            float w1 = W[(4*k4+1)*128 + j];
            float w2 = W[(4*k4+2)*128 + j];
            float w3 = W[(4*k4+3)*128 + j];
            #pragma unroll
            for (int r = 0; r < 32; r++){
                float4 a = *(const float4*)&As[r][4*k4];
                acc[r] = fmaf(a.x, w0, fmaf(a.y, w1, fmaf(a.z, w2, fmaf(a.w, w3, acc[r]))));
            }
        }
        #pragma unroll
        for (int r = 0; r < 32; r++) po[(ro + r)*128 + j] = acc[r];

        // S dots: blocks 108..215 handle (b,c) chunk bid-108
        if (bid >= 108){
            __syncthreads();
            float (*Bs)[129] = (float(*)[129])sbuf;
            float (*Ts)[129] = (float(*)[129])(sbuf + 32*129);
            int bc = bid - 108;
            int r0 = bc * 32;
            for (int idx = tid; idx < 32*128; idx += TPB){
                int rr = idx >> 7, dd = idx & 127;
                Bs[rr][dd] = g_base[r0*DD + idx];
                Ts[rr][dd] = g_tvec[r0*DD + idx];
            }
            __syncthreads();
            for (int p = tid; p < 1024; p += TPB){
                int n = p >> 5, i = p & 31;
                float s = 0.0f;
                #pragma unroll 8
                for (int k = 0; k < 128; k++) s = fmaf(Bs[n][k], Ts[i][k], s);
                g_S[bc*1024 + p] = s;
            }
        }

        // Q projection: blocks 0..127, item (b,i) = bid
        if (bid < 128){
            __syncthreads();
            float* hsq  = sbuf;          // 128
            float* qred = sbuf + 128;    // 256
            int b = bid >> 5, i = bid & 31;
            int r = b*LL + i;
            float mu  = g_mb[r] - g_mt[r];
            float var = (g_ssb[r] - 2.0f*g_sdiag[r] + g_sst[r]) * (1.0f/128.0f) - mu*mu;
            float rstd = rsqrtf(var + 1e-5f);
            if (tid < 128)
                hsq[tid] = (g_base[r*DD+tid] - g_tvec[r*DD+tid] - mu)*rstd*g1[tid] + b1[tid];
            __syncthreads();
            int part = tid >> 7, dp = tid & 127;
            float q = 0.0f;
            int k0 = part*64;
            #pragma unroll
            for (int k = 0; k < 64; k++) q = fmaf(hsq[k0+k], Wq[(k0+k)*128 + dp], q);
            qred[part*128 + dp] = q;
            __syncthreads();
            if (tid < 128) g_Q[bid*DD + tid] = qred[tid] + qred[128+tid] + bq[tid];
        }
    }
    gbar(1);

    // ================= PHASE C: attention per (b,i) + LN2 ====================
    if (bid < 128){
        float* qs    = sbuf;
        float* uks   = sbuf + 128;
        float* cks   = sbuf + 256;
        float* uvs   = sbuf + 384;
        float* cvs   = sbuf + 512;
        float* mus   = sbuf + 640;     // 864
        float* rstds = sbuf + 1504;    // 864
        float* sc    = sbuf + 2368;    // 6912
        float* attp  = sbuf + 9280;    // 256 (also reused as op[2][128])
        float* atts  = sbuf + 9536;    // 128
        float* as_   = sbuf + 9664;    // 128
        float* ysm   = sbuf + 9792;    // 128

        int b = bid >> 5, i = bid & 31;

        if (tid < 128){
            qs[tid]  = g_Q[bid*DD + tid];
            uks[tid] = g_uk[tid]; cks[tid] = g_ck[tid];
            uvs[tid] = g_uv[tid]; cvs[tid] = g_cv[tid];
        }
        if (tid >= 224) mk[tid-224] = mask[b*NN + (tid-224)];

        for (int l = tid; l < LL; l += TPB){
            int c = l >> 5, n = l & 31;
            int rt = b*LL + c*32 + i;
            int rb = b*LL + l;
            float mu  = g_mb[rb] - g_mt[rt];
            float S   = g_S[(b*NCC + c)*1024 + n*32 + i];
            float var = (g_ssb[rb] - 2.0f*S + g_sst[rt]) * (1.0f/128.0f) - mu*mu;
            mus[l]   = mu;
            rstds[l] = rsqrtf(var + 1e-5f);
        }
        if (tid < 128){
            int r = b*LL + i;
            as_[tid] = g_base[r*DD + tid] - g_tvec[r*DD + tid];
        }
        __syncthreads();

        // scores
        for (int idx = tid; idx < LL*HH; idx += TPB){
            int l = idx >> 3, h = idx & 7;
            int c = l >> 5, n = l & 31;
            float mu = mus[l], rstd = rstds[l];
            const float4* Pk4 = (const float4*)&g_Pk[(b*LL + l)*DD + h*16];
            const float4* Tk4 = (const float4*)&g_Tk[(b*LL + c*32 + i)*DD + h*16];
            float s = 0.0f;
            #pragma unroll
            for (int j4 = 0; j4 < 4; j4++){
                float4 p = Pk4[j4], t = Tk4[j4];
                int jb = h*16 + j4*4;
                float k0 = rstd*(p.x - t.x - mu*uks[jb+0]) + cks[jb+0];
                float k1 = rstd*(p.y - t.y - mu*uks[jb+1]) + cks[jb+1];
                float k2 = rstd*(p.z - t.z - mu*uks[jb+2]) + cks[jb+2];
                float k3 = rstd*(p.w - t.w - mu*uks[jb+3]) + cks[jb+3];
                s = fmaf(qs[jb+0], k0, fmaf(qs[jb+1], k1,
                    fmaf(qs[jb+2], k2, fmaf(qs[jb+3], k3, s))));
            }
            s *= 0.25f;
            if (mk[n] == 0) s = -1e9f;
            sc[h*LL + l] = s;
        }
        __syncthreads();

        // softmax: one warp per head (8 warps)
        {
            int w = tid >> 5, lane = tid & 31;
            float m = -3.4e38f;
            for (int l = lane; l < LL; l += 32) m = fmaxf(m, sc[w*LL + l]);
            #pragma unroll
            for (int o = 16; o; o >>= 1) m = fmaxf(m, __shfl_xor_sync(0xffffffffu, m, o));
            float sum = 0.0f;
            for (int l = lane; l < LL; l += 32){
                float e = __expf(sc[w*LL + l] - m);
                sc[w*LL + l] = e;
                sum += e;
            }
            #pragma unroll
            for (int o = 16; o; o >>= 1) sum += __shfl_xor_sync(0xffffffffu, sum, o);
            float inv = 1.0f / sum;
            for (int l = lane; l < LL; l += 32) sc[w*LL + l] *= inv;
        }
        __syncthreads();

        // weighted V (reconstructed), 2-way c-split, dual accumulators
        {
            int d = tid & 127, part = tid >> 7;
            int h = d >> 4;
            float uv = uvs[d], cv = cvs[d];
            float acc0 = 0.0f, acc1 = 0.0f;
            int cbeg = part ? 14 : 0, cend = part ? 27 : 14;
            for (int c = cbeg; c < cend; c++){
                float tv = g_Tv[(b*LL + c*32 + i)*DD + d];
                int lb = c*32;
                #pragma unroll 4
                for (int n = 0; n < 32; n += 2){
                    int l0 = lb + n, l1 = lb + n + 1;
                    float v0 = rstds[l0]*(g_Pv[(b*LL + l0)*DD + d] - tv - mus[l0]*uv) + cv;
                    float v1 = rstds[l1]*(g_Pv[(b*LL + l1)*DD + d] - tv - mus[l1]*uv) + cv;
                    acc0 = fmaf(sc[h*LL + l0], v0, acc0);
                    acc1 = fmaf(sc[h*LL + l1], v1, acc1);
                }
            }
            attp[part*128 + d] = acc0 + acc1;
        }
        __syncthreads();
        if (tid < 128) atts[tid] = attp[tid] + attp[128+tid];
        __syncthreads();

        // output projection (2-way k-split) + residual + LN2
        {
            int dp = tid & 127, part = tid >> 7;
            float o = 0.0f;
            int k0 = part*64;
            #pragma unroll
            for (int k = 0; k < 64; k++) o = fmaf(atts[k0+k], Wo[(k0+k)*128 + dp], o);
            __syncthreads();
            attp[part*128 + dp] = o;   // reuse as op
        }
        __syncthreads();
        if (tid < 128){
            float y = as_[tid] + attp[tid] + attp[128+tid] + bo[tid];
            g_y[bid*DD + tid] = y;
            ysm[tid] = y;
            float s = warpSum(y), s2 = warpSum(y*y);
            if ((tid & 31) == 0){ rsm[tid>>5][0] = s; rsm[tid>>5][1] = s2; }
        }
        __syncthreads();
        if (tid == 0){
            float s  = rsm[0][0]+rsm[1][0]+rsm[2][0]+rsm[3][0];
            float s2 = rsm[0][1]+rsm[1][1]+rsm[2][1]+rsm[3][1];
            float m = s * (1.0f/128.0f);
            stat[0] = m;
            stat[1] = rsqrtf(s2*(1.0f/128.0f) - m*m + 1e-5f);
        }
        __syncthreads();
        if (tid < 128)
            g_hn2[bid*DD + tid] = (ysm[tid] - stat[0])*stat[1]*g2[tid] + b2[tid];
    }
    gbar(2);

    // ================= PHASE D: FFN, 2 rows per block (blocks 0..63) =========
    if (bid < 64){
        float* hs2 = sbuf;          // [2][128]
        float* zs  = sbuf + 256;    // [2][512]
        int r0 = bid*2;
        {
            int row = tid >> 7, dd = tid & 127;
            hs2[row*128 + dd] = g_hn2[(r0+row)*DD + dd];
        }
        __syncthreads();

        // z = relu(hn2 @ W1 + bf1): each thread 2 cols x 2 rows
        {
            int c0 = tid, c1 = tid + 256;
            float z00=0.f, z01=0.f, z10=0.f, z11=0.f;
            #pragma unroll 4
            for (int k = 0; k < 128; k++){
                float w0 = W1[k*DFF + c0];
                float w1 = W1[k*DFF + c1];
                float h0 = hs2[k], h1 = hs2[128+k];
                z00 = fmaf(h0, w0, z00); z01 = fmaf(h0, w1, z01);
                z10 = fmaf(h1, w0, z10); z11 = fmaf(h1, w1, z11);
            }
            zs[c0]       = fmaxf(z00 + bf1[c0], 0.0f);
            zs[c1]       = fmaxf(z01 + bf1[c1], 0.0f);
            zs[512 + c0] = fmaxf(z10 + bf1[c0], 0.0f);
            zs[512 + c1] = fmaxf(z11 + bf1[c1], 0.0f);
        }
        __syncthreads();

        // out = y + z @ W2 + bf2: thread -> (row, col), dual accumulators
        {
            int row = tid >> 7, col = tid & 127;
            const float* zr = zs + row*512;
            float o0 = 0.f, o1 = 0.f;
            #pragma unroll 4
            for (int k = 0; k < 512; k += 2){
                o0 = fmaf(zr[k],   W2[k*128 + col],     o0);
                o1 = fmaf(zr[k+1], W2[(k+1)*128 + col], o1);
            }
            int grow = r0 + row;
            out[grow*DD + col] = g_y[grow*DD + col] + o0 + o1 + bf2[col];
        }
    }
}

// ---------------- launch ------------------------------------------------------
extern "C" void kernel_launch(void* const* d_in, const int* in_sizes, int n_in,
                              void* d_out, int out_size)
{
    const float* x      = (const float*)d_in[0];
    const int*   mask   = (const int*)  d_in[1];
    const float* coords = (const float*)d_in[2];
    const float* Wp = (const float*)d_in[3],  *bp  = (const float*)d_in[4];
    const float* Wq = (const float*)d_in[5],  *bq  = (const float*)d_in[6];
    const float* Wk = (const float*)d_in[7],  *bk  = (const float*)d_in[8];
    const float* Wv = (const float*)d_in[9],  *bv  = (const float*)d_in[10];
    const float* Wo = (const float*)d_in[11], *bo  = (const float*)d_in[12];
    const float* g1 = (const float*)d_in[13], *b1  = (const float*)d_in[14];
    const float* g2 = (const float*)d_in[15], *b2  = (const float*)d_in[16];
    const float* W1 = (const float*)d_in[17], *bf1 = (const float*)d_in[18];
    const float* W2 = (const float*)d_in[19], *bf2 = (const float*)d_in[20];
    float* out = (float*)d_out;

    k_fused<<<GRID, TPB>>>(x, mask, coords, Wp, bp, Wq, bq, Wk, bk, Wv, bv,
                           Wo, bo, g1, b1, g2, b2, W1, bf1, W2, bf2, out);
}

// round 5
// speedup vs baseline: 3.3516x; 3.3516x over previous
#include <cuda_runtime.h>
#include <math.h>

#define BB 4
#define NN 32
#define DD 128
#define HH 8
#define NCC 27
#define DFF 512
#define LL (NCC*NN)        // 864
#define NR (BB*NN)         // 128 token rows

// ---------------- scratch (static device globals; no allocation) -------------
__device__ __align__(16) float g_xb[NR*DD];                 // x + bp
__device__ float g_mxb[NR], g_ssxb[NR];                     // row mean / sumsq of xb
__device__ float g_XW[NR*3];                                // xb @ Wp^T
__device__ __align__(16) float g_Xq[NR*DD], g_Xk[NR*DD], g_Xv[NR*DD];  // (xb*g1)@W
__device__ float g_Mk[3*DD], g_Mv[3*DD];                    // Wp*diag(g1)*W
__device__ float g_uq[DD], g_uk[DD], g_uv[DD];              // g1@W
__device__ float g_cq[DD], g_ck[DD], g_cv[DD];              // b1@W + bias
__device__ float g_G[9], g_rs[3];                           // Wp Wp^T (3x3), Wp row sums
__device__ __align__(16) float g_y[NR*DD], g_hn2[NR*DD];

__inline__ __device__ float warpSum(float v){
    #pragma unroll
    for (int o = 16; o; o >>= 1) v += __shfl_down_sync(0xffffffffu, v, o);
    return v;
}

// ================= K1: all precomputes (131 blocks x 256) =====================
__global__ void __launch_bounds__(256)
k_pre(const float* __restrict__ x,
      const float* __restrict__ Wp, const float* __restrict__ bp,
      const float* __restrict__ Wq, const float* __restrict__ bq,
      const float* __restrict__ Wk, const float* __restrict__ bk,
      const float* __restrict__ Wv, const float* __restrict__ bv,
      const float* __restrict__ g1, const float* __restrict__ b1)
{
    __shared__ float sv[3][128];          // xbg / wpg / g1s+b1s reuse
    __shared__ float red[4][5];
    int bid = blockIdx.x, tid = threadIdx.x;

    if (bid < NR){
        // per-token row: xb, stats, XW, and rows of Xq/Xk/Xv
        if (tid < 128){
            int d = tid;
            float xv = x[bid*DD + d] + bp[d];
            g_xb[bid*DD + d] = xv;
            sv[0][d] = xv * g1[d];
            float w0 = Wp[d], w1 = Wp[DD+d], w2 = Wp[2*DD+d];
            float s  = warpSum(xv),    ss = warpSum(xv*xv);
            float a0 = warpSum(xv*w0), a1 = warpSum(xv*w1), a2 = warpSum(xv*w2);
            int lane = d & 31, w = d >> 5;
            if (lane == 0){ red[w][0]=s; red[w][1]=ss; red[w][2]=a0; red[w][3]=a1; red[w][4]=a2; }
        }
        __syncthreads();
        if (tid < 5){
            float a = red[0][tid]+red[1][tid]+red[2][tid]+red[3][tid];
            if      (tid == 0) g_mxb[bid]  = a * (1.0f/128.0f);
            else if (tid == 1) g_ssxb[bid] = a;
            else               g_XW[bid*3 + (tid-2)] = a;
        }
        __syncthreads();
        for (int o = tid; o < 384; o += 256){
            int m = o >> 7, j = o & 127;
            const float* W = (m==0) ? Wq : ((m==1) ? Wk : Wv);
            float acc = 0.0f;
            #pragma unroll 8
            for (int k = 0; k < 128; k++) acc = fmaf(sv[0][k], W[k*DD + j], acc);
            float* O = (m==0) ? g_Xq : ((m==1) ? g_Xk : g_Xv);
            O[bid*DD + j] = acc;
        }
    } else if (bid == NR){
        // Mk, Mv = (Wp*diag(g1)) @ W
        for (int idx = tid; idx < 384; idx += 256)
            sv[idx>>7][idx&127] = Wp[idx] * g1[idx & 127];
        __syncthreads();
        for (int o = tid; o < 768; o += 256){
            int m = o / 384, rem = o % 384;
            int a = rem >> 7, j = rem & 127;
            const float* W = m ? Wv : Wk;
            float acc = 0.0f;
            #pragma unroll 8
            for (int k = 0; k < 128; k++) acc = fmaf(sv[a][k], W[k*DD + j], acc);
            (m ? g_Mv : g_Mk)[a*DD + j] = acc;
        }
    } else if (bid == NR+1){
        // u = g1@W, c = b1@W + bias, for q/k/v
        if (tid < 128){ sv[0][tid] = g1[tid]; sv[1][tid] = b1[tid]; }
        __syncthreads();
        for (int o = tid; o < 768; o += 256){
            int m = o / 256, rem = o % 256;
            int which = rem >> 7, j = rem & 127;
            const float* W = (m==0) ? Wq : ((m==1) ? Wk : Wv);
            float acc = 0.0f;
            #pragma unroll 8
            for (int k = 0; k < 128; k++) acc = fmaf(sv[which][k], W[k*DD + j], acc);
            if (which == 0) ((m==0) ? g_uq : ((m==1) ? g_uk : g_uv))[j] = acc;
            else {
                const float* bias = (m==0) ? bq : ((m==1) ? bk : bv);
                ((m==0) ? g_cq : ((m==1) ? g_ck : g_cv))[j] = acc + bias[j];
            }
        }
    } else {
        // G = Wp Wp^T (9), rs = Wp row sums (3)
        if (tid < 9){
            int a = tid/3, c = tid%3;
            float acc = 0.0f;
            for (int k = 0; k < 128; k++) acc = fmaf(Wp[a*DD+k], Wp[c*DD+k], acc);
            g_G[tid] = acc;
        } else if (tid < 12){
            int a = tid - 9;
            float acc = 0.0f;
            for (int k = 0; k < 128; k++) acc += Wp[a*DD+k];
            g_rs[a] = acc;
        }
    }
}

// ================= K2: attention per (b,i) — factored form ====================
__global__ void __launch_bounds__(256)
k_attn2(const float* __restrict__ coords, const int* __restrict__ mask,
        const float* __restrict__ Wo, const float* __restrict__ bo,
        const float* __restrict__ uqp, const float* __restrict__ cqp,
        const float* __restrict__ g2, const float* __restrict__ b2)
{
    __shared__ float s_sc[HH][LL];        // 27.6 KB
    __shared__ float s_mu[LL], s_rstd[LL];
    __shared__ float s_q[128];
    __shared__ float s_QXk[HH][32];
    __shared__ float s_qMk[HH][4], s_quk[HH], s_qck[HH];
    __shared__ float s_A[HH][32], s_B[HH][4], s_G8[HH];
    __shared__ float s_mxb[32], s_ssxb[32], s_XW[32][3];
    __shared__ float s_atts[128], s_op[2][128];
    __shared__ float rsm[4][2], stat[2];
    __shared__ int   mk[32];

    int bid = blockIdx.x, tid = threadIdx.x;
    int b = bid >> 5, i = bid & 31;
    const float* cb = coords + b*LL*3;

    if (tid < 32){
        mk[tid]     = mask[b*32 + tid];
        s_mxb[tid]  = g_mxb[b*32 + tid];
        s_ssxb[tid] = g_ssxb[b*32 + tid];
    }
    for (int t = tid; t < 96; t += 256) s_XW[t/3][t%3] = g_XW[b*96 + t];

    // q vector (query row has dc = 0 -> stats are xb's own)
    float mu_i = g_mxb[bid];
    float rstd_i = rsqrtf(g_ssxb[bid]*(1.0f/128.0f) - mu_i*mu_i + 1e-5f);
    if (tid < 128)
        s_q[tid] = rstd_i*g_Xq[bid*DD + tid] - rstd_i*mu_i*uqp[tid] + cqp[tid];
    __syncthreads();

    // per-head dots
    {
        int h = tid >> 5, n = tid & 31;
        float acc = 0.0f;
        #pragma unroll
        for (int j = 0; j < 16; j++)
            acc = fmaf(s_q[h*16+j], g_Xk[(b*32+n)*DD + h*16 + j], acc);
        s_QXk[h][n] = acc;
    }
    if (tid < 24){
        int h = tid/3, a = tid%3;
        float acc = 0.0f;
        #pragma unroll
        for (int j = 0; j < 16; j++) acc = fmaf(s_q[h*16+j], g_Mk[a*DD + h*16 + j], acc);
        s_qMk[h][a] = acc;
    } else if (tid < 32){
        int h = tid - 24;
        float acc = 0.0f;
        #pragma unroll
        for (int j = 0; j < 16; j++) acc = fmaf(s_q[h*16+j], g_uk[h*16+j], acc);
        s_quk[h] = acc;
    } else if (tid < 40){
        int h = tid - 32;
        float acc = 0.0f;
        #pragma unroll
        for (int j = 0; j < 16; j++) acc = fmaf(s_q[h*16+j], g_ck[h*16+j], acc);
        s_qck[h] = acc;
    }
    __syncthreads();

    // scores + LN stats per key
    float Gr[9], rr[3];
    #pragma unroll
    for (int a = 0; a < 9; a++) Gr[a] = g_G[a];
    #pragma unroll
    for (int a = 0; a < 3; a++) rr[a] = g_rs[a] * (1.0f/128.0f);

    for (int l = tid; l < LL; l += 256){
        int c = l >> 5, n = l & 31;
        int lb = l*3, ib = (c*32 + i)*3;
        float d0 = cb[lb]   - cb[ib];
        float d1 = cb[lb+1] - cb[ib+1];
        float d2 = cb[lb+2] - cb[ib+2];
        float mu = s_mxb[n] + d0*rr[0] + d1*rr[1] + d2*rr[2];
        float ss = s_ssxb[n]
                 + 2.0f*(d0*s_XW[n][0] + d1*s_XW[n][1] + d2*s_XW[n][2])
                 + d0*(Gr[0]*d0 + Gr[1]*d1 + Gr[2]*d2)
                 + d1*(Gr[3]*d0 + Gr[4]*d1 + Gr[5]*d2)
                 + d2*(Gr[6]*d0 + Gr[7]*d1 + Gr[8]*d2);
        float var = ss*(1.0f/128.0f) - mu*mu;
        float rstd = rsqrtf(var + 1e-5f);
        s_mu[l] = mu; s_rstd[l] = rstd;
        float rm = rstd*mu;
        bool msk = (mk[n] == 0);
        #pragma unroll
        for (int h = 0; h < 8; h++){
            float s = rstd*(s_QXk[h][n] + d0*s_qMk[h][0] + d1*s_qMk[h][1] + d2*s_qMk[h][2])
                    - rm*s_quk[h] + s_qck[h];
            s *= 0.25f;
            s_sc[h][l] = msk ? -1e9f : s;
        }
    }
    __syncthreads();

    // softmax: warp h over 864
    {
        int h = tid >> 5, lane = tid & 31;
        float m = -3.4e38f;
        for (int l = lane; l < LL; l += 32) m = fmaxf(m, s_sc[h][l]);
        #pragma unroll
        for (int o = 16; o; o >>= 1) m = fmaxf(m, __shfl_xor_sync(0xffffffffu, m, o));
        float sum = 0.0f;
        for (int l = lane; l < LL; l += 32){
            float e = __expf(s_sc[h][l] - m);
            s_sc[h][l] = e;
            sum += e;
        }
        #pragma unroll
        for (int o = 16; o; o >>= 1) sum += __shfl_xor_sync(0xffffffffu, sum, o);
        float inv = 1.0f / sum;
        for (int l = lane; l < LL; l += 32) s_sc[h][l] *= inv;
    }
    __syncthreads();

    // V aggregates: A[h,n], B[h,:], G8[h]
    {
        int h = tid >> 5, n = tid & 31;
        float A = 0.f, B0 = 0.f, B1 = 0.f, B2 = 0.f, Gp = 0.f;
        #pragma unroll 1
        for (int c = 0; c < NCC; c++){
            int l = c*32 + n;
            float w = s_sc[h][l];
            float wr = w * s_rstd[l];
            int lb = l*3, ib = (c*32 + i)*3;
            float d0 = cb[lb] - cb[ib], d1 = cb[lb+1] - cb[ib+1], d2 = cb[lb+2] - cb[ib+2];
            A += wr;
            B0 = fmaf(wr, d0, B0); B1 = fmaf(wr, d1, B1); B2 = fmaf(wr, d2, B2);
            Gp = fmaf(-wr, s_mu[l], Gp);
        }
        s_A[h][n] = A;
        B0 = warpSum(B0); B1 = warpSum(B1); B2 = warpSum(B2); Gp = warpSum(Gp);
        if (n == 0){ s_B[h][0]=B0; s_B[h][1]=B1; s_B[h][2]=B2; s_G8[h]=Gp; }
    }
    __syncthreads();

    // att[d] = sum_n A[h,n]*Xv[n,d] + B[h].Mv[:,d] + G8[h]*uv[d] + cv[d]
    if (tid < 128){
        int d = tid, h = d >> 4;
        float acc = g_cv[d] + s_G8[h]*g_uv[d]
                  + s_B[h][0]*g_Mv[d] + s_B[h][1]*g_Mv[DD+d] + s_B[h][2]*g_Mv[2*DD+d];
        const float* Xvb = g_Xv + b*32*DD;
        #pragma unroll 8
        for (int n = 0; n < 32; n++) acc = fmaf(s_A[h][n], Xvb[n*DD + d], acc);
        s_atts[d] = acc;
    }
    __syncthreads();

    // o = atts @ Wo (2-way k-split), y = xb + o + bo, LN2
    {
        int part = tid >> 7, dp = tid & 127;
        float o = 0.0f;
        int k0 = part*64;
        #pragma unroll
        for (int k = 0; k < 64; k++) o = fmaf(s_atts[k0+k], Wo[(k0+k)*DD + dp], o);
        s_op[part][dp] = o;
    }
    __syncthreads();
    if (tid < 128){
        float y = g_xb[bid*DD + tid] + s_op[0][tid] + s_op[1][tid] + bo[tid];
        g_y[bid*DD + tid] = y;
        s_atts[tid] = y;
        float s = warpSum(y), s2 = warpSum(y*y);
        if ((tid & 31) == 0){ rsm[tid>>5][0] = s; rsm[tid>>5][1] = s2; }
    }
    __syncthreads();
    if (tid == 0){
        float s  = rsm[0][0]+rsm[1][0]+rsm[2][0]+rsm[3][0];
        float s2 = rsm[0][1]+rsm[1][1]+rsm[2][1]+rsm[3][1];
        float m = s * (1.0f/128.0f);
        stat[0] = m;
        stat[1] = rsqrtf(s2*(1.0f/128.0f) - m*m + 1e-5f);
    }
    __syncthreads();
    if (tid < 128)
        g_hn2[bid*DD + tid] = (s_atts[tid] - stat[0])*stat[1]*g2[tid] + b2[tid];
}

// ================= K3: FFN per row (128 blocks x 512) =========================
__global__ void __launch_bounds__(512)
k_ffn(const float* __restrict__ W1, const float* __restrict__ bf1,
      const float* __restrict__ W2, const float* __restrict__ bf2,
      float* __restrict__ out)
{
    __shared__ float hs[128];
    __shared__ float zs[512];
    __shared__ float red[4][128];
    int row = blockIdx.x, tid = threadIdx.x;

    if (tid < 128) hs[tid] = g_hn2[row*DD + tid];
    __syncthreads();

    {
        float z = bf1[tid];
        #pragma unroll 8
        for (int k = 0; k < 128; k++) z = fmaf(hs[k], W1[k*DFF + tid], z);
        zs[tid] = fmaxf(z, 0.0f);
    }
    __syncthreads();

    {
        int part = tid >> 7, d = tid & 127;
        float o = 0.0f;
        int j0 = part*128;
        #pragma unroll 8
        for (int j = 0; j < 128; j++) o = fmaf(zs[j0+j], W2[(j0+j)*DD + d], o);
        red[part][d] = o;
    }
    __syncthreads();
    if (tid < 128)
        out[row*DD + tid] = g_y[row*DD + tid]
                          + red[0][tid] + red[1][tid] + red[2][tid] + red[3][tid]
                          + bf2[tid];
}

// ---------------- launch ------------------------------------------------------
extern "C" void kernel_launch(void* const* d_in, const int* in_sizes, int n_in,
                              void* d_out, int out_size)
{
    const float* x      = (const float*)d_in[0];
    const int*   mask   = (const int*)  d_in[1];
    const float* coords = (const float*)d_in[2];
    const float* Wp = (const float*)d_in[3],  *bp  = (const float*)d_in[4];
    const float* Wq = (const float*)d_in[5],  *bq  = (const float*)d_in[6];
    const float* Wk = (const float*)d_in[7],  *bk  = (const float*)d_in[8];
    const float* Wv = (const float*)d_in[9],  *bv  = (const float*)d_in[10];
    const float* Wo = (const float*)d_in[11], *bo  = (const float*)d_in[12];
    const float* g1 = (const float*)d_in[13], *b1  = (const float*)d_in[14];
    const float* g2 = (const float*)d_in[15], *b2  = (const float*)d_in[16];
    const float* W1 = (const float*)d_in[17], *bf1 = (const float*)d_in[18];
    const float* W2 = (const float*)d_in[19], *bf2 = (const float*)d_in[20];
    float* out = (float*)d_out;

    float *uq_p, *cq_p;
    cudaGetSymbolAddress((void**)&uq_p, g_uq);
    cudaGetSymbolAddress((void**)&cq_p, g_cq);

    k_pre  <<<NR + 3, 256>>>(x, Wp, bp, Wq, bq, Wk, bk, Wv, bv, g1, b1);
    k_attn2<<<NR, 256>>>(coords, mask, Wo, bo, uq_p, cq_p, g2, b2);
    k_ffn  <<<NR, 512>>>(W1, bf1, W2, bf2, out);
}